// round 2
// baseline (speedup 1.0000x reference)
#include <cuda_runtime.h>
#include <math.h>

#define N_NODES 50000
#define N_ENV   1000000
#define N_EDGES 200000
#define NDD     512              // D * N_AXIS = 64*8
#define NODE_OUT_ELEMS (N_NODES * NDD)

// Scratch: per-node accumulators. Layout: [node][3][64] (component-major).
__device__ float g_summ[N_NODES * 192];
__device__ float g_cnt[N_NODES];

__device__ __forceinline__ void red_add_v4(float* p, float a, float b, float c, float d) {
    asm volatile("red.global.add.v4.f32 [%0], {%1,%2,%3,%4};"
                 :: "l"(p), "f"(a), "f"(b), "f"(c), "f"(d) : "memory");
}

__global__ void zero_kernel() {
    int i = blockIdx.x * blockDim.x + threadIdx.x;
    int stride = gridDim.x * blockDim.x;
    float4* p = (float4*)g_summ;
    const float4 z = make_float4(0.f, 0.f, 0.f, 0.f);
    for (int k = i; k < N_NODES * 48; k += stride) p[k] = z;
    for (int k = i; k < N_NODES; k += stride) g_cnt[k] = 0.f;
}

// One thread per environment: smooth cutoff -> 9->32->64->64 tanh MLP (residual
// on last layer) -> outer product with env vector -> vector-atomic scatter.
__global__ void __launch_bounds__(256, 2) env_kernel(
    const float* __restrict__ env_vectors,
    const float* __restrict__ atom_attr,
    const int*   __restrict__ env_index,
    const float* __restrict__ W1, const float* __restrict__ b1,
    const float* __restrict__ W2, const float* __restrict__ b2,
    const float* __restrict__ W3, const float* __restrict__ b3)
{
    __shared__ float sW1[288];
    __shared__ float sb1[32];
    __shared__ float sW2[2048];
    __shared__ float sb2[64];
    __shared__ float sW3[4096];
    __shared__ float sb3[64];

    int tid = threadIdx.x;
    for (int i = tid; i < 288;  i += 256) sW1[i] = W1[i];
    for (int i = tid; i < 32;   i += 256) sb1[i] = b1[i];
    for (int i = tid; i < 2048; i += 256) sW2[i] = W2[i];
    for (int i = tid; i < 64;   i += 256) sb2[i] = b2[i];
    for (int i = tid; i < 4096; i += 256) sW3[i] = W3[i];
    for (int i = tid; i < 64;   i += 256) sb3[i] = b3[i];
    __syncthreads();

    int e = blockIdx.x * 256 + tid;
    if (e >= N_ENV) return;

    float vx = env_vectors[3 * e + 0];
    float vy = env_vectors[3 * e + 1];
    float vz = env_vectors[3 * e + 2];

    // smooth cutoff (RS=3, RC=6)
    float r = sqrtf(vx * vx + vy * vy + vz * vz);
    float inv_r = 1.0f / r;
    float snorm;
    if (r < 3.0f) {
        snorm = inv_r;
    } else if (r < 6.0f) {
        float u = (r - 6.0f) * (-1.0f / 3.0f);     // (r-RC)/(RS-RC)
        snorm = inv_r * (u * u * u * (10.0f + u * (-15.0f + 6.0f * u)) + 1.0f);
    } else {
        snorm = 0.0f;
    }

    int i0 = env_index[e];
    int i1 = env_index[N_ENV + e];

    float4 a0 = *(const float4*)&atom_attr[4 * i0];
    float4 a1 = *(const float4*)&atom_attr[4 * i1];

    float in[9];
    in[0] = snorm;
    in[1] = a0.x; in[2] = a0.y; in[3] = a0.z; in[4] = a0.w;
    in[5] = a1.x; in[6] = a1.y; in[7] = a1.z; in[8] = a1.w;

    // ---- layer 1: 9 -> 32, tanh ----
    float h1[32];
#pragma unroll
    for (int j = 0; j < 32; j += 4) {
        float4 s = *(const float4*)&sb1[j];
#pragma unroll
        for (int i = 0; i < 9; i++) {
            float4 w = *(const float4*)&sW1[i * 32 + j];
            s.x = fmaf(in[i], w.x, s.x);
            s.y = fmaf(in[i], w.y, s.y);
            s.z = fmaf(in[i], w.z, s.z);
            s.w = fmaf(in[i], w.w, s.w);
        }
        h1[j + 0] = tanhf(s.x);
        h1[j + 1] = tanhf(s.y);
        h1[j + 2] = tanhf(s.z);
        h1[j + 3] = tanhf(s.w);
    }

    // ---- layer 2: 32 -> 64, tanh ----
    float h2[64];
#pragma unroll
    for (int j = 0; j < 64; j += 4) {
        float4 s = *(const float4*)&sb2[j];
#pragma unroll
        for (int i = 0; i < 32; i++) {
            float4 w = *(const float4*)&sW2[i * 64 + j];
            s.x = fmaf(h1[i], w.x, s.x);
            s.y = fmaf(h1[i], w.y, s.y);
            s.z = fmaf(h1[i], w.z, s.z);
            s.w = fmaf(h1[i], w.w, s.w);
        }
        h2[j + 0] = tanhf(s.x);
        h2[j + 1] = tanhf(s.y);
        h2[j + 2] = tanhf(s.z);
        h2[j + 3] = tanhf(s.w);
    }

    // ---- layer 3: 64 -> 64, tanh + residual, fused with scatter-add ----
    float* base = &g_summ[(long long)i1 * 192];
#pragma unroll
    for (int j = 0; j < 64; j += 4) {
        float4 s = *(const float4*)&sb3[j];
#pragma unroll
        for (int i = 0; i < 64; i++) {
            float4 w = *(const float4*)&sW3[i * 64 + j];
            s.x = fmaf(h2[i], w.x, s.x);
            s.y = fmaf(h2[i], w.y, s.y);
            s.z = fmaf(h2[i], w.z, s.z);
            s.w = fmaf(h2[i], w.w, s.w);
        }
        float o0 = tanhf(s.x) + h2[j + 0];
        float o1 = tanhf(s.y) + h2[j + 1];
        float o2 = tanhf(s.z) + h2[j + 2];
        float o3 = tanhf(s.w) + h2[j + 3];
        red_add_v4(base +   0 + j, o0 * vx, o1 * vx, o2 * vx, o3 * vx);
        red_add_v4(base +  64 + j, o0 * vy, o1 * vy, o2 * vy, o3 * vy);
        red_add_v4(base + 128 + j, o0 * vz, o1 * vz, o2 * vz, o3 * vz);
    }
    atomicAdd(&g_cnt[i1], 1.0f);
}

// 4 nodes per 256-thread block; 64 threads (one per dim d) per node.
// aggr[c][d] = summ[n][c][d] / max(cnt,1); out[n, d*8+a] = sum_c aggr[c][d]*aggr[c][a]
__global__ void __launch_bounds__(256) node_kernel(float* __restrict__ out)
{
    int t = threadIdx.x;
    int local = t >> 6;            // 0..3
    int d = t & 63;
    int n = blockIdx.x * 4 + local;   // N_NODES % 4 == 0, no partial blocks

    __shared__ float sA[4][3][8];

    float cnt = g_cnt[n];
    float inv = 1.0f / fmaxf(cnt, 1.0f);
    const float* base = &g_summ[(long long)n * 192];
    float c0 = base[  0 + d] * inv;
    float c1 = base[ 64 + d] * inv;
    float c2 = base[128 + d] * inv;

    if (d < 8) {
        sA[local][0][d] = c0;
        sA[local][1][d] = c1;
        sA[local][2][d] = c2;
    }
    __syncthreads();

    float res[8];
#pragma unroll
    for (int a = 0; a < 8; a++) {
        res[a] = c0 * sA[local][0][a] + c1 * sA[local][1][a] + c2 * sA[local][2][a];
    }

    float4* op = (float4*)&out[(long long)n * NDD + d * 8];
    op[0] = make_float4(res[0], res[1], res[2], res[3]);
    op[1] = make_float4(res[4], res[5], res[6], res[7]);
}

// 2 edges per 256-thread block; 128 threads (one float4 each) per edge.
__global__ void __launch_bounds__(256) edge_kernel(
    const int* __restrict__ edge_index,
    const float* __restrict__ node_desc,
    float* __restrict__ out)
{
    int t = threadIdx.x;
    int k = blockIdx.x * 2 + (t >> 7);
    int lane = t & 127;
    if (k >= N_EDGES) return;

    int i = edge_index[k];
    int j = edge_index[N_EDGES + k];

    float4 x = ((const float4*)&node_desc[(long long)i * NDD])[lane];
    float4 y = ((const float4*)&node_desc[(long long)j * NDD])[lane];
    float4 r = make_float4(x.x + y.x, x.y + y.y, x.z + y.z, x.w + y.w);
    ((float4*)&out[(long long)k * NDD])[lane] = r;
}

extern "C" void kernel_launch(void* const* d_in, const int* in_sizes, int n_in,
                              void* d_out, int out_size)
{
    const float* env_vectors = (const float*)d_in[0];
    const float* atom_attr   = (const float*)d_in[1];
    const int*   env_index   = (const int*)  d_in[2];
    const int*   edge_index  = (const int*)  d_in[3];
    const float* W1 = (const float*)d_in[4];
    const float* b1 = (const float*)d_in[5];
    const float* W2 = (const float*)d_in[6];
    const float* b2 = (const float*)d_in[7];
    const float* W3 = (const float*)d_in[8];
    const float* b3 = (const float*)d_in[9];

    float* out = (float*)d_out;
    float* node_out = out;                       // [50000, 512]
    float* edge_out = out + NODE_OUT_ELEMS;      // [200000, 512]

    zero_kernel<<<2048, 256>>>();
    env_kernel<<<(N_ENV + 255) / 256, 256>>>(env_vectors, atom_attr, env_index,
                                             W1, b1, W2, b2, W3, b3);
    node_kernel<<<N_NODES / 4, 256>>>(node_out);
    edge_kernel<<<N_EDGES / 2, 256>>>(edge_index, node_out, edge_out);
}

// round 6
// speedup vs baseline: 1.1088x; 1.1088x over previous
#include <cuda_runtime.h>
#include <math.h>

#define N_NODES 50000
#define N_ENV   1000000
#define N_EDGES 200000
#define NDD     512              // D * N_AXIS = 64*8
#define NODE_OUT_ELEMS (N_NODES * NDD)

// Scratch: per-node accumulators. Layout: [node][3][64] (component-major).
__device__ float g_summ[N_NODES * 192];
__device__ float g_cnt[N_NODES];

typedef unsigned long long u64;

__device__ __forceinline__ u64 pack2(float lo, float hi) {
    u64 r; asm("mov.b64 %0, {%1,%2};" : "=l"(r) : "f"(lo), "f"(hi)); return r;
}
__device__ __forceinline__ void unpack2(u64 v, float& lo, float& hi) {
    asm("mov.b64 {%0,%1}, %2;" : "=f"(lo), "=f"(hi) : "l"(v));
}
__device__ __forceinline__ u64 fma2(u64 a, u64 b, u64 c) {
    u64 d; asm("fma.rn.f32x2 %0, %1, %2, %3;" : "=l"(d) : "l"(a), "l"(b), "l"(c)); return d;
}
__device__ __forceinline__ float tanh_fast(float x) {
    float y; asm("tanh.approx.f32 %0, %1;" : "=f"(y) : "f"(x)); return y;
}

__device__ __forceinline__ void red_add_v4(float* p, float a, float b, float c, float d) {
    asm volatile("red.global.add.v4.f32 [%0], {%1,%2,%3,%4};"
                 :: "l"(p), "f"(a), "f"(b), "f"(c), "f"(d) : "memory");
}

__global__ void zero_kernel() {
    int i = blockIdx.x * blockDim.x + threadIdx.x;
    int stride = gridDim.x * blockDim.x;
    float4* p = (float4*)g_summ;
    const float4 z = make_float4(0.f, 0.f, 0.f, 0.f);
    for (int k = i; k < N_NODES * 48; k += stride) p[k] = z;
    for (int k = i; k < N_NODES; k += stride) g_cnt[k] = 0.f;
}

// One thread per environment: smooth cutoff -> 9->32->64->64 tanh MLP (residual
// on last layer) -> outer product with env vector -> vector-atomic scatter.
// Inner products use packed fma.rn.f32x2 (2 output neurons per op).
__global__ void __launch_bounds__(256, 2) env_kernel(
    const float* __restrict__ env_vectors,
    const float* __restrict__ atom_attr,
    const int*   __restrict__ env_index,
    const float* __restrict__ W1, const float* __restrict__ b1,
    const float* __restrict__ W2, const float* __restrict__ b2,
    const float* __restrict__ W3, const float* __restrict__ b3)
{
    __shared__ __align__(16) float sW1[288];
    __shared__ __align__(16) float sb1[32];
    __shared__ __align__(16) float sW2[2048];
    __shared__ __align__(16) float sb2[64];
    __shared__ __align__(16) float sW3[4096];
    __shared__ __align__(16) float sb3[64];

    int tid = threadIdx.x;
    for (int i = tid; i < 288;  i += 256) sW1[i] = W1[i];
    for (int i = tid; i < 32;   i += 256) sb1[i] = b1[i];
    for (int i = tid; i < 2048; i += 256) sW2[i] = W2[i];
    for (int i = tid; i < 64;   i += 256) sb2[i] = b2[i];
    for (int i = tid; i < 4096; i += 256) sW3[i] = W3[i];
    for (int i = tid; i < 64;   i += 256) sb3[i] = b3[i];
    __syncthreads();

    int e = blockIdx.x * 256 + tid;
    if (e >= N_ENV) return;

    float vx = env_vectors[3 * e + 0];
    float vy = env_vectors[3 * e + 1];
    float vz = env_vectors[3 * e + 2];

    // smooth cutoff (RS=3, RC=6)
    float r = sqrtf(vx * vx + vy * vy + vz * vz);
    float inv_r = 1.0f / r;
    float snorm;
    if (r < 3.0f) {
        snorm = inv_r;
    } else if (r < 6.0f) {
        float u = (r - 6.0f) * (-1.0f / 3.0f);     // (r-RC)/(RS-RC)
        snorm = inv_r * (u * u * u * (10.0f + u * (-15.0f + 6.0f * u)) + 1.0f);
    } else {
        snorm = 0.0f;
    }

    int i0 = env_index[e];
    int i1 = env_index[N_ENV + e];

    float4 a0 = *(const float4*)&atom_attr[4 * i0];
    float4 a1 = *(const float4*)&atom_attr[4 * i1];

    // packed broadcast inputs
    u64 inp[9];
    inp[0] = pack2(snorm, snorm);
    inp[1] = pack2(a0.x, a0.x); inp[2] = pack2(a0.y, a0.y);
    inp[3] = pack2(a0.z, a0.z); inp[4] = pack2(a0.w, a0.w);
    inp[5] = pack2(a1.x, a1.x); inp[6] = pack2(a1.y, a1.y);
    inp[7] = pack2(a1.z, a1.z); inp[8] = pack2(a1.w, a1.w);

    // ---- layer 1: 9 -> 32, tanh ----
    float h1[32];
#pragma unroll
    for (int j = 0; j < 32; j += 4) {
        ulonglong2 b = *(const ulonglong2*)&sb1[j];
        u64 s0 = b.x, s1 = b.y;
#pragma unroll
        for (int i = 0; i < 9; i++) {
            ulonglong2 w = *(const ulonglong2*)&sW1[i * 32 + j];
            s0 = fma2(inp[i], w.x, s0);
            s1 = fma2(inp[i], w.y, s1);
        }
        float x0, x1, x2, x3;
        unpack2(s0, x0, x1); unpack2(s1, x2, x3);
        h1[j + 0] = tanh_fast(x0);
        h1[j + 1] = tanh_fast(x1);
        h1[j + 2] = tanh_fast(x2);
        h1[j + 3] = tanh_fast(x3);
    }

    u64 h1p[32];
#pragma unroll
    for (int i = 0; i < 32; i++) h1p[i] = pack2(h1[i], h1[i]);

    // ---- layer 2: 32 -> 64, tanh ----
    float h2[64];
#pragma unroll
    for (int j = 0; j < 64; j += 4) {
        ulonglong2 b = *(const ulonglong2*)&sb2[j];
        u64 s0 = b.x, s1 = b.y;
#pragma unroll
        for (int i = 0; i < 32; i++) {
            ulonglong2 w = *(const ulonglong2*)&sW2[i * 64 + j];
            s0 = fma2(h1p[i], w.x, s0);
            s1 = fma2(h1p[i], w.y, s1);
        }
        float x0, x1, x2, x3;
        unpack2(s0, x0, x1); unpack2(s1, x2, x3);
        h2[j + 0] = tanh_fast(x0);
        h2[j + 1] = tanh_fast(x1);
        h2[j + 2] = tanh_fast(x2);
        h2[j + 3] = tanh_fast(x3);
    }

    u64 h2p[64];
#pragma unroll
    for (int i = 0; i < 64; i++) h2p[i] = pack2(h2[i], h2[i]);

    // ---- layer 3: 64 -> 64, tanh + residual, fused with scatter-add ----
    float* base = &g_summ[(long long)i1 * 192];
#pragma unroll
    for (int j = 0; j < 64; j += 4) {
        ulonglong2 b = *(const ulonglong2*)&sb3[j];
        u64 s0 = b.x, s1 = b.y;
#pragma unroll
        for (int i = 0; i < 64; i++) {
            ulonglong2 w = *(const ulonglong2*)&sW3[i * 64 + j];
            s0 = fma2(h2p[i], w.x, s0);
            s1 = fma2(h2p[i], w.y, s1);
        }
        float x0, x1, x2, x3;
        unpack2(s0, x0, x1); unpack2(s1, x2, x3);
        float o0 = tanh_fast(x0) + h2[j + 0];
        float o1 = tanh_fast(x1) + h2[j + 1];
        float o2 = tanh_fast(x2) + h2[j + 2];
        float o3 = tanh_fast(x3) + h2[j + 3];
        red_add_v4(base +   0 + j, o0 * vx, o1 * vx, o2 * vx, o3 * vx);
        red_add_v4(base +  64 + j, o0 * vy, o1 * vy, o2 * vy, o3 * vy);
        red_add_v4(base + 128 + j, o0 * vz, o1 * vz, o2 * vz, o3 * vz);
    }
    atomicAdd(&g_cnt[i1], 1.0f);
}

// 4 nodes per 256-thread block; 64 threads (one per dim d) per node.
// aggr[c][d] = summ[n][c][d] / max(cnt,1); out[n, d*8+a] = sum_c aggr[c][d]*aggr[c][a]
__global__ void __launch_bounds__(256) node_kernel(float* __restrict__ out)
{
    int t = threadIdx.x;
    int local = t >> 6;            // 0..3
    int d = t & 63;
    int n = blockIdx.x * 4 + local;   // N_NODES % 4 == 0, no partial blocks

    __shared__ float sA[4][3][8];

    float cnt = g_cnt[n];
    float inv = 1.0f / fmaxf(cnt, 1.0f);
    const float* base = &g_summ[(long long)n * 192];
    float c0 = base[  0 + d] * inv;
    float c1 = base[ 64 + d] * inv;
    float c2 = base[128 + d] * inv;

    if (d < 8) {
        sA[local][0][d] = c0;
        sA[local][1][d] = c1;
        sA[local][2][d] = c2;
    }
    __syncthreads();

    float res[8];
#pragma unroll
    for (int a = 0; a < 8; a++) {
        res[a] = c0 * sA[local][0][a] + c1 * sA[local][1][a] + c2 * sA[local][2][a];
    }

    float4* op = (float4*)&out[(long long)n * NDD + d * 8];
    op[0] = make_float4(res[0], res[1], res[2], res[3]);
    op[1] = make_float4(res[4], res[5], res[6], res[7]);
}

// 2 edges per 256-thread block; 128 threads (one float4 each) per edge.
__global__ void __launch_bounds__(256) edge_kernel(
    const int* __restrict__ edge_index,
    const float* __restrict__ node_desc,
    float* __restrict__ out)
{
    int t = threadIdx.x;
    int k = blockIdx.x * 2 + (t >> 7);
    int lane = t & 127;
    if (k >= N_EDGES) return;

    int i = edge_index[k];
    int j = edge_index[N_EDGES + k];

    float4 x = ((const float4*)&node_desc[(long long)i * NDD])[lane];
    float4 y = ((const float4*)&node_desc[(long long)j * NDD])[lane];
    float4 r = make_float4(x.x + y.x, x.y + y.y, x.z + y.z, x.w + y.w);
    ((float4*)&out[(long long)k * NDD])[lane] = r;
}

extern "C" void kernel_launch(void* const* d_in, const int* in_sizes, int n_in,
                              void* d_out, int out_size)
{
    const float* env_vectors = (const float*)d_in[0];
    const float* atom_attr   = (const float*)d_in[1];
    const int*   env_index   = (const int*)  d_in[2];
    const int*   edge_index  = (const int*)  d_in[3];
    const float* W1 = (const float*)d_in[4];
    const float* b1 = (const float*)d_in[5];
    const float* W2 = (const float*)d_in[6];
    const float* b2 = (const float*)d_in[7];
    const float* W3 = (const float*)d_in[8];
    const float* b3 = (const float*)d_in[9];

    float* out = (float*)d_out;
    float* node_out = out;                       // [50000, 512]
    float* edge_out = out + NODE_OUT_ELEMS;      // [200000, 512]

    zero_kernel<<<2048, 256>>>();
    env_kernel<<<(N_ENV + 255) / 256, 256>>>(env_vectors, atom_attr, env_index,
                                             W1, b1, W2, b2, W3, b3);
    node_kernel<<<N_NODES / 4, 256>>>(node_out);
    edge_kernel<<<N_EDGES / 2, 256>>>(edge_index, node_out, edge_out);
}

// round 7
// speedup vs baseline: 1.5567x; 1.4039x over previous
#include <cuda_runtime.h>
#include <math.h>

#define N_NODES 50000
#define N_ENV   1000000
#define N_EDGES 200000
#define NDD     512              // D * N_AXIS = 64*8
#define NODE_OUT_ELEMS (N_NODES * NDD)

// Scratch: per-node accumulators. Layout: [node][3][64] (component-major).
__device__ float g_summ[N_NODES * 192];
__device__ float g_cnt[N_NODES];

typedef unsigned long long u64;
typedef unsigned int u32;

__device__ __forceinline__ u64 pack2(float lo, float hi) {
    u64 r; asm("mov.b64 %0, {%1,%2};" : "=l"(r) : "f"(lo), "f"(hi)); return r;
}
__device__ __forceinline__ void unpack2(u64 v, float& lo, float& hi) {
    asm("mov.b64 {%0,%1}, %2;" : "=f"(lo), "=f"(hi) : "l"(v));
}
__device__ __forceinline__ u64 fma2(u64 a, u64 b, u64 c) {
    u64 d; asm("fma.rn.f32x2 %0, %1, %2, %3;" : "=l"(d) : "l"(a), "l"(b), "l"(c)); return d;
}
__device__ __forceinline__ float tanh_fast(float x) {
    float y; asm("tanh.approx.f32 %0, %1;" : "=f"(y) : "f"(x)); return y;
}
__device__ __forceinline__ u32 to_tf32(float x) {
    u32 u; asm("cvt.rna.tf32.f32 %0, %1;" : "=r"(u) : "f"(x)); return u;
}
__device__ __forceinline__ void red_add_v2(float* p, float a, float b) {
    asm volatile("red.global.add.v2.f32 [%0], {%1,%2};"
                 :: "l"(p), "f"(a), "f"(b) : "memory");
}
// D/C frag: c0=(row=gid,col=2tg) c1=(gid,2tg+1) c2=(gid+8,2tg) c3=(gid+8,2tg+1)
// A frag (16x8 row-major): a0=(gid,tg) a1=(gid+8,tg) a2=(gid,tg+4) a3=(gid+8,tg+4)
// B frag (8x8 col):        b0=(k=tg,n=gid) b1=(k=tg+4,n=gid)
__device__ __forceinline__ void mma_tf32(float* d, u32 a0, u32 a1, u32 a2, u32 a3,
                                         u32 b0, u32 b1) {
    asm volatile(
        "mma.sync.aligned.m16n8k8.row.col.f32.tf32.tf32.f32 "
        "{%0,%1,%2,%3},{%4,%5,%6,%7},{%8,%9},{%0,%1,%2,%3};"
        : "+f"(d[0]), "+f"(d[1]), "+f"(d[2]), "+f"(d[3])
        : "r"(a0), "r"(a1), "r"(a2), "r"(a3), "r"(b0), "r"(b1));
}

__global__ void zero_kernel() {
    int i = blockIdx.x * blockDim.x + threadIdx.x;
    int stride = gridDim.x * blockDim.x;
    float4* p = (float4*)g_summ;
    const float4 z = make_float4(0.f, 0.f, 0.f, 0.f);
    for (int k = i; k < N_NODES * 48; k += stride) p[k] = z;
    for (int k = i; k < N_NODES; k += stride) g_cnt[k] = 0.f;
}

// Dynamic smem layout (floats)
#define OFF_W1 0                 // 288
#define OFF_B1 288               // 32
#define OFF_B2 320               // 64
#define OFF_B3 384               // 64
#define OFF_W2 448               // 32 x 72 (tf32-rounded, stride 72 -> tg*8+gid banks)
#define OFF_W3 2752              // 64 x 72 (tf32-rounded)
#define OFF_H  7360              // 8 warps x [32 envs][68] f32 (stride 68 -> 4*gid+tg banks)
#define SMEM_FLOATS (7360 + 8 * 32 * 68)   // 24768 floats = 99072 B
#define N_WARPS_TOTAL (N_ENV / 32)         // 31250 exactly

__global__ void __launch_bounds__(256, 2) env_kernel(
    const float* __restrict__ env_vectors,
    const float* __restrict__ atom_attr,
    const int*   __restrict__ env_index,
    const float* __restrict__ W1, const float* __restrict__ b1,
    const float* __restrict__ W2, const float* __restrict__ b2,
    const float* __restrict__ W3, const float* __restrict__ b3)
{
    extern __shared__ __align__(16) float sm[];
    int tid = threadIdx.x;

    // ---- stage weights; W2/W3 pre-rounded to tf32, padded strides ----
    for (int i = tid; i < 288; i += 256) sm[OFF_W1 + i] = W1[i];
    for (int i = tid; i < 32;  i += 256) sm[OFF_B1 + i] = b1[i];
    for (int i = tid; i < 64;  i += 256) sm[OFF_B2 + i] = b2[i];
    for (int i = tid; i < 64;  i += 256) sm[OFF_B3 + i] = b3[i];
    for (int i = tid; i < 2048; i += 256) {
        int k = i >> 6, n = i & 63;
        sm[OFF_W2 + k * 72 + n] = __uint_as_float(to_tf32(W2[i]));
    }
    for (int i = tid; i < 4096; i += 256) {
        int k = i >> 6, n = i & 63;
        sm[OFF_W3 + k * 72 + n] = __uint_as_float(to_tf32(W3[i]));
    }
    __syncthreads();

    int wid  = tid >> 5;
    int lane = tid & 31;
    int warpg = blockIdx.x * 8 + wid;
    if (warpg >= N_WARPS_TOTAL) return;
    int e_base = warpg * 32;

    float* H = &sm[OFF_H + wid * (32 * 68)];
    const float* sW1 = &sm[OFF_W1];
    const float* sb1 = &sm[OFF_B1];

    // ================= scalar layer 1 (exact fp32), lane = env =================
    {
        int e = e_base + lane;
        float vx = env_vectors[3 * e + 0];
        float vy = env_vectors[3 * e + 1];
        float vz = env_vectors[3 * e + 2];
        float r = sqrtf(vx * vx + vy * vy + vz * vz);
        float inv_r = 1.0f / r;
        float snorm;
        if (r < 3.0f) snorm = inv_r;
        else if (r < 6.0f) {
            float u = (r - 6.0f) * (-1.0f / 3.0f);
            snorm = inv_r * (u * u * u * (10.0f + u * (-15.0f + 6.0f * u)) + 1.0f);
        } else snorm = 0.0f;

        int i0 = env_index[e];
        int i1 = env_index[N_ENV + e];
        float4 a0 = *(const float4*)&atom_attr[4 * i0];
        float4 a1 = *(const float4*)&atom_attr[4 * i1];

        u64 inp[9];
        inp[0] = pack2(snorm, snorm);
        inp[1] = pack2(a0.x, a0.x); inp[2] = pack2(a0.y, a0.y);
        inp[3] = pack2(a0.z, a0.z); inp[4] = pack2(a0.w, a0.w);
        inp[5] = pack2(a1.x, a1.x); inp[6] = pack2(a1.y, a1.y);
        inp[7] = pack2(a1.z, a1.z); inp[8] = pack2(a1.w, a1.w);

        float h1[32];
#pragma unroll
        for (int j = 0; j < 32; j += 4) {
            ulonglong2 b = *(const ulonglong2*)&sb1[j];
            u64 s0 = b.x, s1 = b.y;
#pragma unroll
            for (int i = 0; i < 9; i++) {
                ulonglong2 w = *(const ulonglong2*)&sW1[i * 32 + j];
                s0 = fma2(inp[i], w.x, s0);
                s1 = fma2(inp[i], w.y, s1);
            }
            float x0, x1, x2, x3;
            unpack2(s0, x0, x1); unpack2(s1, x2, x3);
            h1[j + 0] = tanh_fast(x0);
            h1[j + 1] = tanh_fast(x1);
            h1[j + 2] = tanh_fast(x2);
            h1[j + 3] = tanh_fast(x3);
        }
        // stage h1 as A-tile rows: H[env_local=lane][k]
#pragma unroll
        for (int k = 0; k < 32; k += 2)
            *(float2*)&H[lane * 68 + k] = make_float2(h1[k], h1[k + 1]);
    }
    __syncwarp();

    int gid = lane >> 2;       // 0..7
    int tg  = lane & 3;        // 0..3
    const float* sW2 = &sm[OFF_W2];
    const float* sW3 = &sm[OFF_W3];
    const float* sb2 = &sm[OFF_B2];
    const float* sb3 = &sm[OFF_B3];

    // ================= two 16-env M-tiles through tf32 mma =================
    for (int m = 0; m < 2; m++) {
        int rA = (m * 16 + gid) * 68;       // row of env gid
        int rB = (m * 16 + gid + 8) * 68;   // row of env gid+8

        // ---- layer 2: [16 envs] x [64 out], K=32 ----
        float h2[8][4];
#pragma unroll
        for (int nt = 0; nt < 8; nt++) {
            float bb0 = sb2[nt * 8 + tg * 2], bb1 = sb2[nt * 8 + tg * 2 + 1];
            h2[nt][0] = bb0; h2[nt][1] = bb1; h2[nt][2] = bb0; h2[nt][3] = bb1;
        }
#pragma unroll
        for (int kt = 0; kt < 4; kt++) {
            u32 fa0 = to_tf32(H[rA + kt * 8 + tg]);
            u32 fa1 = to_tf32(H[rB + kt * 8 + tg]);
            u32 fa2 = to_tf32(H[rA + kt * 8 + tg + 4]);
            u32 fa3 = to_tf32(H[rB + kt * 8 + tg + 4]);
#pragma unroll
            for (int nt = 0; nt < 8; nt++) {
                u32 fb0 = __float_as_uint(sW2[(kt * 8 + tg) * 72 + nt * 8 + gid]);
                u32 fb1 = __float_as_uint(sW2[(kt * 8 + tg + 4) * 72 + nt * 8 + gid]);
                mma_tf32(h2[nt], fa0, fa1, fa2, fa3, fb0, fb1);
            }
        }
        // tanh in-place -> h2 (kept in regs for residual), stage to smem for layer-3 A
#pragma unroll
        for (int nt = 0; nt < 8; nt++) {
            h2[nt][0] = tanh_fast(h2[nt][0]);
            h2[nt][1] = tanh_fast(h2[nt][1]);
            h2[nt][2] = tanh_fast(h2[nt][2]);
            h2[nt][3] = tanh_fast(h2[nt][3]);
        }
        __syncwarp();   // everyone done reading h1 rows of this m-tile
#pragma unroll
        for (int nt = 0; nt < 8; nt++) {
            *(float2*)&H[rA + nt * 8 + tg * 2] = make_float2(h2[nt][0], h2[nt][1]);
            *(float2*)&H[rB + nt * 8 + tg * 2] = make_float2(h2[nt][2], h2[nt][3]);
        }
        __syncwarp();

        // ---- layer 3: [16 envs] x [64 out], K=64 ----
        float d3[8][4];
#pragma unroll
        for (int nt = 0; nt < 8; nt++) {
            float bb0 = sb3[nt * 8 + tg * 2], bb1 = sb3[nt * 8 + tg * 2 + 1];
            d3[nt][0] = bb0; d3[nt][1] = bb1; d3[nt][2] = bb0; d3[nt][3] = bb1;
        }
#pragma unroll
        for (int kt = 0; kt < 8; kt++) {
            u32 fa0 = to_tf32(H[rA + kt * 8 + tg]);
            u32 fa1 = to_tf32(H[rB + kt * 8 + tg]);
            u32 fa2 = to_tf32(H[rA + kt * 8 + tg + 4]);
            u32 fa3 = to_tf32(H[rB + kt * 8 + tg + 4]);
#pragma unroll
            for (int nt = 0; nt < 8; nt++) {
                u32 fb0 = __float_as_uint(sW3[(kt * 8 + tg) * 72 + nt * 8 + gid]);
                u32 fb1 = __float_as_uint(sW3[(kt * 8 + tg + 4) * 72 + nt * 8 + gid]);
                mma_tf32(d3[nt], fa0, fa1, fa2, fa3, fb0, fb1);
            }
        }

        // ---- epilogue: tanh + residual, outer with v, scatter (red.v2) ----
        int eA = e_base + m * 16 + gid;
        int eB = eA + 8;
        float vAx = env_vectors[3 * eA + 0], vAy = env_vectors[3 * eA + 1], vAz = env_vectors[3 * eA + 2];
        float vBx = env_vectors[3 * eB + 0], vBy = env_vectors[3 * eB + 1], vBz = env_vectors[3 * eB + 2];
        int nA = env_index[N_ENV + eA];
        int nB = env_index[N_ENV + eB];
        float* baseA = &g_summ[(long long)nA * 192];
        float* baseB = &g_summ[(long long)nB * 192];

#pragma unroll
        for (int nt = 0; nt < 8; nt++) {
            int off = nt * 8 + tg * 2;
            float oA0 = tanh_fast(d3[nt][0]) + h2[nt][0];
            float oA1 = tanh_fast(d3[nt][1]) + h2[nt][1];
            float oB0 = tanh_fast(d3[nt][2]) + h2[nt][2];
            float oB1 = tanh_fast(d3[nt][3]) + h2[nt][3];
            red_add_v2(baseA +   0 + off, oA0 * vAx, oA1 * vAx);
            red_add_v2(baseA +  64 + off, oA0 * vAy, oA1 * vAy);
            red_add_v2(baseA + 128 + off, oA0 * vAz, oA1 * vAz);
            red_add_v2(baseB +   0 + off, oB0 * vBx, oB1 * vBx);
            red_add_v2(baseB +  64 + off, oB0 * vBy, oB1 * vBy);
            red_add_v2(baseB + 128 + off, oB0 * vBz, oB1 * vBz);
        }
        if (tg == 0) {
            atomicAdd(&g_cnt[nA], 1.0f);
            atomicAdd(&g_cnt[nB], 1.0f);
        }
    }
}

// 4 nodes per 256-thread block; 64 threads (one per dim d) per node.
__global__ void __launch_bounds__(256) node_kernel(float* __restrict__ out)
{
    int t = threadIdx.x;
    int local = t >> 6;
    int d = t & 63;
    int n = blockIdx.x * 4 + local;

    __shared__ float sA[4][3][8];

    float cnt = g_cnt[n];
    float inv = 1.0f / fmaxf(cnt, 1.0f);
    const float* base = &g_summ[(long long)n * 192];
    float c0 = base[  0 + d] * inv;
    float c1 = base[ 64 + d] * inv;
    float c2 = base[128 + d] * inv;

    if (d < 8) {
        sA[local][0][d] = c0;
        sA[local][1][d] = c1;
        sA[local][2][d] = c2;
    }
    __syncthreads();

    float res[8];
#pragma unroll
    for (int a = 0; a < 8; a++)
        res[a] = c0 * sA[local][0][a] + c1 * sA[local][1][a] + c2 * sA[local][2][a];

    float4* op = (float4*)&out[(long long)n * NDD + d * 8];
    op[0] = make_float4(res[0], res[1], res[2], res[3]);
    op[1] = make_float4(res[4], res[5], res[6], res[7]);
}

__device__ __forceinline__ void st_cs_v4(float* p, float4 v) {
    asm volatile("st.global.cs.v4.f32 [%0], {%1,%2,%3,%4};"
                 :: "l"(p), "f"(v.x), "f"(v.y), "f"(v.z), "f"(v.w) : "memory");
}

// 2 edges per 256-thread block; streaming stores keep node_desc L2-resident.
__global__ void __launch_bounds__(256) edge_kernel(
    const int* __restrict__ edge_index,
    const float* __restrict__ node_desc,
    float* __restrict__ out)
{
    int t = threadIdx.x;
    int k = blockIdx.x * 2 + (t >> 7);
    int lane = t & 127;
    if (k >= N_EDGES) return;

    int i = edge_index[k];
    int j = edge_index[N_EDGES + k];

    float4 x = ((const float4*)&node_desc[(long long)i * NDD])[lane];
    float4 y = ((const float4*)&node_desc[(long long)j * NDD])[lane];
    float4 r = make_float4(x.x + y.x, x.y + y.y, x.z + y.z, x.w + y.w);
    st_cs_v4(&out[(long long)k * NDD + lane * 4], r);
}

extern "C" void kernel_launch(void* const* d_in, const int* in_sizes, int n_in,
                              void* d_out, int out_size)
{
    const float* env_vectors = (const float*)d_in[0];
    const float* atom_attr   = (const float*)d_in[1];
    const int*   env_index   = (const int*)  d_in[2];
    const int*   edge_index  = (const int*)  d_in[3];
    const float* W1 = (const float*)d_in[4];
    const float* b1 = (const float*)d_in[5];
    const float* W2 = (const float*)d_in[6];
    const float* b2 = (const float*)d_in[7];
    const float* W3 = (const float*)d_in[8];
    const float* b3 = (const float*)d_in[9];

    float* out = (float*)d_out;
    float* node_out = out;                       // [50000, 512]
    float* edge_out = out + NODE_OUT_ELEMS;      // [200000, 512]

    size_t smem_bytes = SMEM_FLOATS * sizeof(float);   // 99072
    cudaFuncSetAttribute(env_kernel, cudaFuncAttributeMaxDynamicSharedMemorySize,
                         (int)smem_bytes);

    zero_kernel<<<2048, 256>>>();
    int n_ctas = (N_WARPS_TOTAL + 7) / 8;   // 3907
    env_kernel<<<n_ctas, 256, smem_bytes>>>(env_vectors, atom_attr, env_index,
                                            W1, b1, W2, b2, W3, b3);
    node_kernel<<<N_NODES / 4, 256>>>(node_out);
    edge_kernel<<<N_EDGES / 2, 256>>>(edge_index, node_out, edge_out);
}

// round 9
// speedup vs baseline: 1.6681x; 1.0716x over previous
#include <cuda_runtime.h>
#include <math.h>

#define N_NODES 50000
#define N_ENV   1000000
#define N_EDGES 200000
#define NDD     512              // D * N_AXIS = 64*8
#define NODE_OUT_ELEMS (N_NODES * NDD)

// Scratch: per-node accumulators. Layout: [node][3][64] (component-major).
// After node_kernel this holds the MEAN (aggr) in place.
__device__ float g_summ[N_NODES * 192];
__device__ float g_cnt[N_NODES];

typedef unsigned long long u64;
typedef unsigned int u32;

__device__ __forceinline__ u64 pack2(float lo, float hi) {
    u64 r; asm("mov.b64 %0, {%1,%2};" : "=l"(r) : "f"(lo), "f"(hi)); return r;
}
__device__ __forceinline__ void unpack2(u64 v, float& lo, float& hi) {
    asm("mov.b64 {%0,%1}, %2;" : "=f"(lo), "=f"(hi) : "l"(v));
}
__device__ __forceinline__ u64 fma2(u64 a, u64 b, u64 c) {
    u64 d; asm("fma.rn.f32x2 %0, %1, %2, %3;" : "=l"(d) : "l"(a), "l"(b), "l"(c)); return d;
}
__device__ __forceinline__ float tanh_fast(float x) {
    float y; asm("tanh.approx.f32 %0, %1;" : "=f"(y) : "f"(x)); return y;
}
__device__ __forceinline__ u32 to_tf32(float x) {
    u32 u; asm("cvt.rna.tf32.f32 %0, %1;" : "=r"(u) : "f"(x)); return u;
}
__device__ __forceinline__ void red_add_v4(float* p, float a, float b, float c, float d) {
    asm volatile("red.global.add.v4.f32 [%0], {%1,%2,%3,%4};"
                 :: "l"(p), "f"(a), "f"(b), "f"(c), "f"(d) : "memory");
}
// D/C frag: c0=(row=gid,col=2tg) c1=(gid,2tg+1) c2=(gid+8,2tg) c3=(gid+8,2tg+1)
// A frag (16x8 row-major): a0=(gid,tg) a1=(gid+8,tg) a2=(gid,tg+4) a3=(gid+8,tg+4)
// B frag (8x8 col):        b0=(k=tg,n=gid) b1=(k=tg+4,n=gid)
__device__ __forceinline__ void mma_tf32(float* d, u32 a0, u32 a1, u32 a2, u32 a3,
                                         u32 b0, u32 b1) {
    asm volatile(
        "mma.sync.aligned.m16n8k8.row.col.f32.tf32.tf32.f32 "
        "{%0,%1,%2,%3},{%4,%5,%6,%7},{%8,%9},{%0,%1,%2,%3};"
        : "+f"(d[0]), "+f"(d[1]), "+f"(d[2]), "+f"(d[3])
        : "r"(a0), "r"(a1), "r"(a2), "r"(a3), "r"(b0), "r"(b1));
}

__global__ void zero_kernel() {
    int i = blockIdx.x * blockDim.x + threadIdx.x;
    int stride = gridDim.x * blockDim.x;
    float4* p = (float4*)g_summ;
    const float4 z = make_float4(0.f, 0.f, 0.f, 0.f);
    for (int k = i; k < N_NODES * 48; k += stride) p[k] = z;
    for (int k = i; k < N_NODES; k += stride) g_cnt[k] = 0.f;
}

// Dynamic smem layout (floats)
#define OFF_W1 0                 // 288
#define OFF_B1 288               // 32
#define OFF_B2 320               // 64
#define OFF_B3 384               // 64
#define OFF_W2 448               // 32 x 72 (tf32-rounded)
#define OFF_W3 2752              // 64 x 72 (tf32-rounded)
#define OFF_H  7360              // 8 warps x [32 envs][68] f32
#define SMEM_FLOATS (7360 + 8 * 32 * 68)   // 24768 floats = 99072 B
#define N_WARPS_TOTAL (N_ENV / 32)         // 31250 exactly

__global__ void __launch_bounds__(256, 2) env_kernel(
    const float* __restrict__ env_vectors,
    const float* __restrict__ atom_attr,
    const int*   __restrict__ env_index,
    const float* __restrict__ W1, const float* __restrict__ b1,
    const float* __restrict__ W2, const float* __restrict__ b2,
    const float* __restrict__ W3, const float* __restrict__ b3)
{
    extern __shared__ __align__(16) float sm[];
    int tid = threadIdx.x;

    for (int i = tid; i < 288; i += 256) sm[OFF_W1 + i] = W1[i];
    for (int i = tid; i < 32;  i += 256) sm[OFF_B1 + i] = b1[i];
    for (int i = tid; i < 64;  i += 256) sm[OFF_B2 + i] = b2[i];
    for (int i = tid; i < 64;  i += 256) sm[OFF_B3 + i] = b3[i];
    for (int i = tid; i < 2048; i += 256) {
        int k = i >> 6, n = i & 63;
        sm[OFF_W2 + k * 72 + n] = __uint_as_float(to_tf32(W2[i]));
    }
    for (int i = tid; i < 4096; i += 256) {
        int k = i >> 6, n = i & 63;
        sm[OFF_W3 + k * 72 + n] = __uint_as_float(to_tf32(W3[i]));
    }
    __syncthreads();

    int wid  = tid >> 5;
    int lane = tid & 31;
    int warpg = blockIdx.x * 8 + wid;
    if (warpg >= N_WARPS_TOTAL) return;
    int e_base = warpg * 32;

    float* H = &sm[OFF_H + wid * (32 * 68)];
    const float* sW1 = &sm[OFF_W1];
    const float* sb1 = &sm[OFF_B1];

    // ================= scalar layer 1 (exact fp32), lane = env =================
    {
        int e = e_base + lane;
        float vx = env_vectors[3 * e + 0];
        float vy = env_vectors[3 * e + 1];
        float vz = env_vectors[3 * e + 2];
        float r = sqrtf(vx * vx + vy * vy + vz * vz);
        float inv_r = 1.0f / r;
        float snorm;
        if (r < 3.0f) snorm = inv_r;
        else if (r < 6.0f) {
            float u = (r - 6.0f) * (-1.0f / 3.0f);
            snorm = inv_r * (u * u * u * (10.0f + u * (-15.0f + 6.0f * u)) + 1.0f);
        } else snorm = 0.0f;

        int i0 = env_index[e];
        int i1 = env_index[N_ENV + e];
        float4 a0 = *(const float4*)&atom_attr[4 * i0];
        float4 a1 = *(const float4*)&atom_attr[4 * i1];

        u64 inp[9];
        inp[0] = pack2(snorm, snorm);
        inp[1] = pack2(a0.x, a0.x); inp[2] = pack2(a0.y, a0.y);
        inp[3] = pack2(a0.z, a0.z); inp[4] = pack2(a0.w, a0.w);
        inp[5] = pack2(a1.x, a1.x); inp[6] = pack2(a1.y, a1.y);
        inp[7] = pack2(a1.z, a1.z); inp[8] = pack2(a1.w, a1.w);

        float h1[32];
#pragma unroll
        for (int j = 0; j < 32; j += 4) {
            ulonglong2 b = *(const ulonglong2*)&sb1[j];
            u64 s0 = b.x, s1 = b.y;
#pragma unroll
            for (int i = 0; i < 9; i++) {
                ulonglong2 w = *(const ulonglong2*)&sW1[i * 32 + j];
                s0 = fma2(inp[i], w.x, s0);
                s1 = fma2(inp[i], w.y, s1);
            }
            float x0, x1, x2, x3;
            unpack2(s0, x0, x1); unpack2(s1, x2, x3);
            h1[j + 0] = tanh_fast(x0);
            h1[j + 1] = tanh_fast(x1);
            h1[j + 2] = tanh_fast(x2);
            h1[j + 3] = tanh_fast(x3);
        }
#pragma unroll
        for (int k = 0; k < 32; k += 2)
            *(float2*)&H[lane * 68 + k] = make_float2(h1[k], h1[k + 1]);
    }
    __syncwarp();

    int gid = lane >> 2;       // 0..7
    int tg  = lane & 3;        // 0..3
    const float* sW2 = &sm[OFF_W2];
    const float* sW3 = &sm[OFF_W3];
    const float* sb2 = &sm[OFF_B2];
    const float* sb3 = &sm[OFF_B3];

    for (int m = 0; m < 2; m++) {
        int rA = (m * 16 + gid) * 68;
        int rB = (m * 16 + gid + 8) * 68;

        // ---- layer 2: K=32 ----
        float h2[8][4];
#pragma unroll
        for (int nt = 0; nt < 8; nt++) {
            float bb0 = sb2[nt * 8 + tg * 2], bb1 = sb2[nt * 8 + tg * 2 + 1];
            h2[nt][0] = bb0; h2[nt][1] = bb1; h2[nt][2] = bb0; h2[nt][3] = bb1;
        }
#pragma unroll
        for (int kt = 0; kt < 4; kt++) {
            u32 fa0 = to_tf32(H[rA + kt * 8 + tg]);
            u32 fa1 = to_tf32(H[rB + kt * 8 + tg]);
            u32 fa2 = to_tf32(H[rA + kt * 8 + tg + 4]);
            u32 fa3 = to_tf32(H[rB + kt * 8 + tg + 4]);
#pragma unroll
            for (int nt = 0; nt < 8; nt++) {
                u32 fb0 = __float_as_uint(sW2[(kt * 8 + tg) * 72 + nt * 8 + gid]);
                u32 fb1 = __float_as_uint(sW2[(kt * 8 + tg + 4) * 72 + nt * 8 + gid]);
                mma_tf32(h2[nt], fa0, fa1, fa2, fa3, fb0, fb1);
            }
        }
#pragma unroll
        for (int nt = 0; nt < 8; nt++) {
            h2[nt][0] = tanh_fast(h2[nt][0]);
            h2[nt][1] = tanh_fast(h2[nt][1]);
            h2[nt][2] = tanh_fast(h2[nt][2]);
            h2[nt][3] = tanh_fast(h2[nt][3]);
        }
        __syncwarp();
#pragma unroll
        for (int nt = 0; nt < 8; nt++) {
            *(float2*)&H[rA + nt * 8 + tg * 2] = make_float2(h2[nt][0], h2[nt][1]);
            *(float2*)&H[rB + nt * 8 + tg * 2] = make_float2(h2[nt][2], h2[nt][3]);
        }
        __syncwarp();

        // ---- layer 3: K=64 ----
        float d3[8][4];
#pragma unroll
        for (int nt = 0; nt < 8; nt++) {
            float bb0 = sb3[nt * 8 + tg * 2], bb1 = sb3[nt * 8 + tg * 2 + 1];
            d3[nt][0] = bb0; d3[nt][1] = bb1; d3[nt][2] = bb0; d3[nt][3] = bb1;
        }
#pragma unroll
        for (int kt = 0; kt < 8; kt++) {
            u32 fa0 = to_tf32(H[rA + kt * 8 + tg]);
            u32 fa1 = to_tf32(H[rB + kt * 8 + tg]);
            u32 fa2 = to_tf32(H[rA + kt * 8 + tg + 4]);
            u32 fa3 = to_tf32(H[rB + kt * 8 + tg + 4]);
#pragma unroll
            for (int nt = 0; nt < 8; nt++) {
                u32 fb0 = __float_as_uint(sW3[(kt * 8 + tg) * 72 + nt * 8 + gid]);
                u32 fb1 = __float_as_uint(sW3[(kt * 8 + tg + 4) * 72 + nt * 8 + gid]);
                mma_tf32(d3[nt], fa0, fa1, fa2, fa3, fb0, fb1);
            }
        }

        // ---- epilogue: tanh+residual, pair-shuffle to 4-wide, red.v4 scatter ----
        int eA = e_base + m * 16 + gid;
        int eB = eA + 8;
        // even tg handles row eA (4 contiguous cols), odd tg handles row eB
        int odd = tg & 1;
        int e_use = odd ? eB : eA;
        float vx = env_vectors[3 * e_use + 0];
        float vy = env_vectors[3 * e_use + 1];
        float vz = env_vectors[3 * e_use + 2];
        int n_use = env_index[N_ENV + e_use];
        float* base = &g_summ[(long long)n_use * 192];
        int col4 = (tg & 2) * 2;   // 0 or 4

#pragma unroll
        for (int nt = 0; nt < 8; nt++) {
            float oA0 = tanh_fast(d3[nt][0]) + h2[nt][0];
            float oA1 = tanh_fast(d3[nt][1]) + h2[nt][1];
            float oB0 = tanh_fast(d3[nt][2]) + h2[nt][2];
            float oB1 = tanh_fast(d3[nt][3]) + h2[nt][3];
            float pA0 = __shfl_xor_sync(0xffffffff, oA0, 1);
            float pA1 = __shfl_xor_sync(0xffffffff, oA1, 1);
            float pB0 = __shfl_xor_sync(0xffffffff, oB0, 1);
            float pB1 = __shfl_xor_sync(0xffffffff, oB1, 1);
            float q0 = odd ? pB0 : oA0;
            float q1 = odd ? pB1 : oA1;
            float q2 = odd ? oB0 : pA0;
            float q3 = odd ? oB1 : pA1;
            int off = nt * 8 + col4;
            red_add_v4(base +   0 + off, q0 * vx, q1 * vx, q2 * vx, q3 * vx);
            red_add_v4(base +  64 + off, q0 * vy, q1 * vy, q2 * vy, q3 * vy);
            red_add_v4(base + 128 + off, q0 * vz, q1 * vz, q2 * vz, q3 * vz);
        }
        if (tg == 0) {
            atomicAdd(&g_cnt[env_index[N_ENV + eA]], 1.0f);
            atomicAdd(&g_cnt[env_index[N_ENV + eB]], 1.0f);
        }
    }
}

// 4 nodes per 256-thread block. Computes aggr (mean), writes node_desc, AND
// writes aggr back into g_summ in place for the edge kernel to reuse.
__global__ void __launch_bounds__(256) node_kernel(float* __restrict__ out)
{
    int t = threadIdx.x;
    int local = t >> 6;
    int d = t & 63;
    int n = blockIdx.x * 4 + local;

    __shared__ float sA[4][3][8];

    float cnt = g_cnt[n];
    float inv = 1.0f / fmaxf(cnt, 1.0f);
    float* base = &g_summ[(long long)n * 192];
    float c0 = base[  0 + d] * inv;
    float c1 = base[ 64 + d] * inv;
    float c2 = base[128 + d] * inv;

    if (d < 8) {
        sA[local][0][d] = c0;
        sA[local][1][d] = c1;
        sA[local][2][d] = c2;
    }
    // write aggr in place (each thread touches only its own 3 elements)
    base[  0 + d] = c0;
    base[ 64 + d] = c1;
    base[128 + d] = c2;
    __syncthreads();

    float res[8];
#pragma unroll
    for (int a = 0; a < 8; a++)
        res[a] = c0 * sA[local][0][a] + c1 * sA[local][1][a] + c2 * sA[local][2][a];

    float4* op = (float4*)&out[(long long)n * NDD + d * 8];
    op[0] = make_float4(res[0], res[1], res[2], res[3]);
    op[1] = make_float4(res[4], res[5], res[6], res[7]);
}

__device__ __forceinline__ void st_cs_v4(float* p, float4 v) {
    asm volatile("st.global.cs.v4.f32 [%0], {%1,%2,%3,%4};"
                 :: "l"(p), "f"(v.x), "f"(v.y), "f"(v.z), "f"(v.w) : "memory");
}

// 4 edges per 256-thread block; recompute both endpoint descriptors from the
// small (38MB, L2-resident) aggr buffer instead of gathering 2KB node_desc rows.
__global__ void __launch_bounds__(256) edge_kernel(
    const int* __restrict__ edge_index,
    float* __restrict__ out)
{
    int t = threadIdx.x;
    int g = t >> 6;            // 0..3
    int d = t & 63;
    int k = blockIdx.x * 4 + g;   // N_EDGES % 4 == 0

    __shared__ float sA[4][2][3][8];

    int i = edge_index[k];
    int j = edge_index[N_EDGES + k];
    const float* Ai = &g_summ[(long long)i * 192];
    const float* Aj = &g_summ[(long long)j * 192];
    float ai0 = Ai[d], ai1 = Ai[64 + d], ai2 = Ai[128 + d];
    float aj0 = Aj[d], aj1 = Aj[64 + d], aj2 = Aj[128 + d];

    if (d < 8) {
        sA[g][0][0][d] = ai0; sA[g][0][1][d] = ai1; sA[g][0][2][d] = ai2;
        sA[g][1][0][d] = aj0; sA[g][1][1][d] = aj1; sA[g][1][2][d] = aj2;
    }
    __syncthreads();

    float res[8];
#pragma unroll
    for (int a = 0; a < 8; a++) {
        res[a] = ai0 * sA[g][0][0][a] + ai1 * sA[g][0][1][a] + ai2 * sA[g][0][2][a]
               + aj0 * sA[g][1][0][a] + aj1 * sA[g][1][1][a] + aj2 * sA[g][1][2][a];
    }

    float* op = &out[(long long)k * NDD + d * 8];
    st_cs_v4(op,     make_float4(res[0], res[1], res[2], res[3]));
    st_cs_v4(op + 4, make_float4(res[4], res[5], res[6], res[7]));
}

extern "C" void kernel_launch(void* const* d_in, const int* in_sizes, int n_in,
                              void* d_out, int out_size)
{
    const float* env_vectors = (const float*)d_in[0];
    const float* atom_attr   = (const float*)d_in[1];
    const int*   env_index   = (const int*)  d_in[2];
    const int*   edge_index  = (const int*)  d_in[3];
    const float* W1 = (const float*)d_in[4];
    const float* b1 = (const float*)d_in[5];
    const float* W2 = (const float*)d_in[6];
    const float* b2 = (const float*)d_in[7];
    const float* W3 = (const float*)d_in[8];
    const float* b3 = (const float*)d_in[9];

    float* out = (float*)d_out;
    float* node_out = out;                       // [50000, 512]
    float* edge_out = out + NODE_OUT_ELEMS;      // [200000, 512]

    size_t smem_bytes = SMEM_FLOATS * sizeof(float);   // 99072
    cudaFuncSetAttribute(env_kernel, cudaFuncAttributeMaxDynamicSharedMemorySize,
                         (int)smem_bytes);

    zero_kernel<<<2048, 256>>>();
    int n_ctas = (N_WARPS_TOTAL + 7) / 8;   // 3907
    env_kernel<<<n_ctas, 256, smem_bytes>>>(env_vectors, atom_attr, env_index,
                                            W1, b1, W2, b2, W3, b3);
    node_kernel<<<N_NODES / 4, 256>>>(node_out);
    edge_kernel<<<N_EDGES / 4, 256>>>(edge_index, edge_out);
}